// round 4
// baseline (speedup 1.0000x reference)
#include <cuda_runtime.h>
#include <cstdint>

// ViT patch embedding via mma.sync tf32 (sm_103 PTX target — tcgen05 unavailable).
// GEMM M=25088, N=768, K=768 fused with patchify gather + bias + cls scatter.
// BM=BN=128, BK=32, warp tile 64x64 (4 warps), double-buffered cp.async,
// 2 blocks/SM. W pre-rounded to tf32 (rna) -> no cvt on B operands.

#define NPATCH  196
#define NIMG    128
#define KDIM    768
#define NDIM    768
#define MTOT    25088

#define BM 128
#define BN 128
#define BK 32
#define KSTRIDE 36                 // padded smem row stride (floats)
#define NITER (KDIM / BK)          // 24
#define TILE_F (BM * KSTRIDE)      // floats per buffer side
#define SMEM_BYTES (4 * TILE_F * 4)  // A[2] + B[2]

__device__ float W_pre[NDIM * KDIM];

__device__ __forceinline__ uint32_t f2tf(float x) {
    uint32_t r;
    asm("cvt.rna.tf32.f32 %0, %1;" : "=r"(r) : "f"(x));
    return r;
}
__device__ __forceinline__ void mma_tf32(float* c, const uint32_t* a, const uint32_t* b) {
    asm volatile(
        "mma.sync.aligned.m16n8k8.row.col.f32.tf32.tf32.f32 "
        "{%0,%1,%2,%3}, {%4,%5,%6,%7}, {%8,%9}, {%0,%1,%2,%3};\n"
        : "+f"(c[0]), "+f"(c[1]), "+f"(c[2]), "+f"(c[3])
        : "r"(a[0]), "r"(a[1]), "r"(a[2]), "r"(a[3]), "r"(b[0]), "r"(b[1]));
}
__device__ __forceinline__ void cp16(uint32_t s, const void* g) {
    asm volatile("cp.async.cg.shared.global [%0], [%1], 16;\n" :: "r"(s), "l"(g));
}
__device__ __forceinline__ void cp_commit() { asm volatile("cp.async.commit_group;\n"); }
template <int N>
__device__ __forceinline__ void cp_wait() { asm volatile("cp.async.wait_group %0;\n" :: "n"(N)); }

__global__ void round_w(const float* __restrict__ W) {
    int i = blockIdx.x * 256 + threadIdx.x;
    if (i < NDIM * KDIM) {
        uint32_t r;
        asm("cvt.rna.tf32.f32 %0, %1;" : "=r"(r) : "f"(W[i]));
        W_pre[i] = __uint_as_float(r);
    }
}

__global__ __launch_bounds__(128, 2) void vit_gemm(
    const float* __restrict__ images,
    const float* __restrict__ bias,
    const float* __restrict__ cls,
    float* __restrict__ out)
{
    extern __shared__ __align__(16) float sm[];
    float* As = sm;                 // [2][BM][KSTRIDE]
    float* Bs = sm + 2 * TILE_F;    // [2][BN][KSTRIDE]

    const int tid  = threadIdx.x;
    const int lane = tid & 31;
    const int warp = tid >> 5;
    const int wr   = warp >> 1;     // 0..1 -> 64 rows
    const int wc   = warp & 1;      // 0..1 -> 64 cols
    const int g    = lane >> 2;     // 0..7
    const int tg   = lane & 3;      // 0..3

    const int bm = blockIdx.y * BM;
    const int bn = blockIdx.x * BN;

    // loader: thread t owns row t of both tiles (8 cp16 each)
    {
    }
    const int m0    = bm + tid;
    const int img0  = m0 / NPATCH;
    const int pch0  = m0 - img0 * NPATCH;
    const int Pi0   = pch0 / 14;
    const int Pj0   = pch0 - Pi0 * 14;
    const float* abase = images + (size_t)img0 * 150528 + (size_t)(Pi0 * 16) * 224 + Pj0 * 16;
    const float* bbase = W_pre + (size_t)(bn + tid) * KDIM;

    const uint32_t sA = (uint32_t)__cvta_generic_to_shared(As);
    const uint32_t sB = (uint32_t)__cvta_generic_to_shared(Bs);
    const uint32_t rowOff = (uint32_t)tid * (KSTRIDE * 4);
    const uint32_t bufB = TILE_F * 4;

    auto load_tile = [&](int buf, int it) {
        const int k0  = it * BK;
        const int c   = k0 >> 8;
        const int ph0 = (k0 >> 4) & 15;
        const float* ag = abase + c * 50176 + ph0 * 224;
        const float* bg = bbase + k0;
        const uint32_t sa = sA + buf * bufB + rowOff;
        const uint32_t sb = sB + buf * bufB + rowOff;
        #pragma unroll
        for (int ch = 0; ch < 8; ++ch) {
            cp16(sa + ch * 16, ag + (ch >> 2) * 224 + (ch & 3) * 4);
            cp16(sb + ch * 16, bg + ch * 4);
        }
    };

    float acc[4][8][4];
    #pragma unroll
    for (int mt = 0; mt < 4; ++mt)
        #pragma unroll
        for (int nt = 0; nt < 8; ++nt)
            #pragma unroll
            for (int r = 0; r < 4; ++r) acc[mt][nt][r] = 0.f;

    load_tile(0, 0);
    cp_commit();

    #define AS(b, r, c) As[(b) * TILE_F + (r) * KSTRIDE + (c)]
    #define BS(b, r, c) Bs[(b) * TILE_F + (r) * KSTRIDE + (c)]

    for (int it = 0; it < NITER; ++it) {
        const int buf = it & 1;
        if (it + 1 < NITER) {
            load_tile(buf ^ 1, it + 1);
            cp_commit();
            cp_wait<1>();
        } else {
            cp_wait<0>();
        }
        __syncthreads();

        #pragma unroll
        for (int ks = 0; ks < 4; ++ks) {
            const int kb = ks * 8;
            uint32_t af[4][4], bf[8][2];
            #pragma unroll
            for (int mt = 0; mt < 4; ++mt) {
                const int row = wr * 64 + mt * 16;
                af[mt][0] = f2tf(AS(buf, row + g,     kb + tg));
                af[mt][1] = f2tf(AS(buf, row + g + 8, kb + tg));
                af[mt][2] = f2tf(AS(buf, row + g,     kb + tg + 4));
                af[mt][3] = f2tf(AS(buf, row + g + 8, kb + tg + 4));
            }
            #pragma unroll
            for (int nt = 0; nt < 8; ++nt) {
                const int col = wc * 64 + nt * 8;
                bf[nt][0] = __float_as_uint(BS(buf, col + g, kb + tg));
                bf[nt][1] = __float_as_uint(BS(buf, col + g, kb + tg + 4));
            }
            #pragma unroll
            for (int mt = 0; mt < 4; ++mt)
                #pragma unroll
                for (int nt = 0; nt < 8; ++nt)
                    mma_tf32(acc[mt][nt], af[mt], bf[nt]);
        }
        __syncthreads();
    }

    // ---- epilogue: bias + scatter ----
    float bv[8][2];
    #pragma unroll
    for (int nt = 0; nt < 8; ++nt) {
        const int col = bn + wc * 64 + nt * 8 + tg * 2;
        bv[nt][0] = bias[col];
        bv[nt][1] = bias[col + 1];
    }

    #pragma unroll
    for (int mt = 0; mt < 4; ++mt) {
        #pragma unroll
        for (int rh = 0; rh < 2; ++rh) {
            const int m     = bm + wr * 64 + mt * 16 + rh * 8 + g;
            const int img   = m / NPATCH;
            const int patch = m - img * NPATCH;
            float* orow = out + ((size_t)img * 197 + patch + 1) * NDIM;
            #pragma unroll
            for (int nt = 0; nt < 8; ++nt) {
                const int col = bn + wc * 64 + nt * 8 + tg * 2;
                float2 v;
                v.x = acc[mt][nt][rh * 2 + 0] + bv[nt][0];
                v.y = acc[mt][nt][rh * 2 + 1] + bv[nt][1];
                *reinterpret_cast<float2*>(orow + col) = v;
            }
        }
    }

    // ---- fused CLS rows (first-wave blocks only) ----
    if (blockIdx.y == 0) {
        const int gid = blockIdx.x * 128 + tid;            // 0..767
        const float4* c4 = (const float4*)cls;
        for (int i = gid; i < NIMG * (NDIM / 4); i += 768) {
            const int img = i / (NDIM / 4);
            const int n4  = i - img * (NDIM / 4);
            reinterpret_cast<float4*>(out + (size_t)img * 197 * NDIM)[n4] = c4[n4];
        }
    }
}

extern "C" void kernel_launch(void* const* d_in, const int* in_sizes, int n_in,
                              void* d_out, int out_size) {
    const float* images = (const float*)d_in[0];
    const float* W      = (const float*)d_in[1];
    const float* b      = (const float*)d_in[2];
    const float* cls    = (const float*)d_in[3];
    float* out          = (float*)d_out;

    cudaFuncSetAttribute(vit_gemm, cudaFuncAttributeMaxDynamicSharedMemorySize, SMEM_BYTES);

    round_w<<<(NDIM * KDIM + 255) / 256, 256>>>(W);
    dim3 grid(NDIM / BN, MTOT / BM);   // (6, 196), n fastest for A L2 reuse
    vit_gemm<<<grid, 128, SMEM_BYTES>>>(images, b, cls, out);
}

// round 5
// speedup vs baseline: 1.0231x; 1.0231x over previous
#include <cuda_runtime.h>
#include <cstdint>

// ViT patch embedding, mma.sync tf32 (fallback HMMA path; tcgen05 not supported
// by this toolchain's sm_103 PTX target).
// GEMM M=25088, N=768, K=768, fused patchify + bias + cls.
// BM=BN=128, BK=16, 4-stage cp.async ring, 256 threads (warp tile 32x64),
// 2 blocks/SM. W pre-rounded to tf32 AND pair-permuted so B fragments are LDS.64.
// A fragments rely on HW tf32 truncation (no cvt in mainloop).

#define NPATCH  196
#define NIMG    128
#define KDIM    768
#define NDIM    768
#define MTOT    25088

#define BM 128
#define BN 128
#define BK 16
#define NITER (KDIM / BK)      // 48
#define ASTR 20                // A smem row stride (floats): (20g+tg)%32 distinct
#define BSTR 24                // B smem row stride (floats): (24g+2tg)%32 distinct/half-warp
#define ASTAGE (BM * ASTR)     // 2560 floats
#define BSTAGE (BM * BSTR)     // 3072 floats
#define NSTG 4
#define SMEM_BYTES ((NSTG * (ASTAGE + BSTAGE)) * 4)   // 90112 B

__device__ float W_pre[NDIM * KDIM];

__device__ __forceinline__ void mma_tf32(float* c, const uint32_t* a, const uint32_t* b) {
    asm volatile(
        "mma.sync.aligned.m16n8k8.row.col.f32.tf32.tf32.f32 "
        "{%0,%1,%2,%3}, {%4,%5,%6,%7}, {%8,%9}, {%0,%1,%2,%3};\n"
        : "+f"(c[0]), "+f"(c[1]), "+f"(c[2]), "+f"(c[3])
        : "r"(a[0]), "r"(a[1]), "r"(a[2]), "r"(a[3]), "r"(b[0]), "r"(b[1]));
}
__device__ __forceinline__ void cp16(uint32_t s, const void* g) {
    asm volatile("cp.async.cg.shared.global [%0], [%1], 16;\n" :: "r"(s), "l"(g));
}
__device__ __forceinline__ void cp_commit() { asm volatile("cp.async.commit_group;\n"); }
template <int N>
__device__ __forceinline__ void cp_wait() { asm volatile("cp.async.wait_group %0;\n" :: "n"(N)); }

// Pre-round W to tf32 (rna) and permute within each 8-k group so that
// (k, k+4) land adjacent: dst = (k & ~7) | ((k&3)*2 + ((k>>2)&1)).
__global__ void round_w(const float* __restrict__ W) {
    int i = blockIdx.x * 256 + threadIdx.x;
    if (i < NDIM * KDIM) {
        int n = i / KDIM, k = i - n * KDIM;
        int kp = (k & ~7) | ((k & 3) * 2 + ((k >> 2) & 1));
        uint32_t r;
        asm("cvt.rna.tf32.f32 %0, %1;" : "=r"(r) : "f"(W[i]));
        W_pre[n * KDIM + kp] = __uint_as_float(r);
    }
}

__global__ __launch_bounds__(256, 2) void vit_gemm(
    const float* __restrict__ images,
    const float* __restrict__ bias,
    const float* __restrict__ cls,
    float* __restrict__ out)
{
    extern __shared__ __align__(16) float sm[];
    float* As = sm;                       // [NSTG][BM][ASTR]
    float* Bs = sm + NSTG * ASTAGE;       // [NSTG][BN][BSTR]

    const int tid  = threadIdx.x;
    const int lane = tid & 31;
    const int warp = tid >> 5;
    const int wm   = warp >> 1;     // 0..3 -> 32 rows
    const int wn   = warp & 1;      // 0..1 -> 64 cols
    const int g    = lane >> 2;     // 0..7
    const int tg   = lane & 3;      // 0..3

    const int bm = blockIdx.y * BM;
    const int bn = blockIdx.x * BN;

    // ---- loader mapping: 512 cp16 per side per stage; row = tid&127, 2 chunks ----
    const int lr = tid & 127;
    const int q0 = (tid >> 7) * 2;   // chunks q0, q0+1 (of 4 per 16-float row)

    const int m0   = bm + lr;
    const int img0 = m0 / NPATCH;
    const int pch0 = m0 - img0 * NPATCH;
    const int Pi0  = pch0 / 14;
    const int Pj0  = pch0 - Pi0 * 14;
    const float* abase = images + (size_t)img0 * 150528 + (size_t)(Pi0 * 16) * 224 + Pj0 * 16 + q0 * 4;
    const float* bbase = W_pre + (size_t)(bn + lr) * KDIM + q0 * 4;

    const uint32_t sA = (uint32_t)__cvta_generic_to_shared(As);
    const uint32_t sB = (uint32_t)__cvta_generic_to_shared(Bs);
    const uint32_t aoff = (uint32_t)(lr * ASTR + q0 * 4) * 4;
    const uint32_t boff = (uint32_t)(lr * BSTR + q0 * 4) * 4;

    auto load_tile = [&](int it) {
        const int st = it & (NSTG - 1);
        const int k0 = it * BK;
        const int c  = k0 >> 8;              // channel
        const int ph = (k0 >> 4) & 15;       // row within patch
        const float* ag = abase + c * 50176 + ph * 224;
        const float* bg = bbase + k0;
        const uint32_t sa = sA + st * (ASTAGE * 4) + aoff;
        const uint32_t sb = sB + st * (BSTAGE * 4) + boff;
        cp16(sa,      ag);
        cp16(sa + 16, ag + 4);
        cp16(sb,      bg);
        cp16(sb + 16, bg + 4);
    };

    float acc[2][8][4];
    #pragma unroll
    for (int mt = 0; mt < 2; ++mt)
        #pragma unroll
        for (int nt = 0; nt < 8; ++nt)
            #pragma unroll
            for (int r = 0; r < 4; ++r) acc[mt][nt][r] = 0.f;

    load_tile(0); cp_commit();
    load_tile(1); cp_commit();
    load_tile(2); cp_commit();

    for (int it = 0; it < NITER; ++it) {
        if (it < NITER - 2)      cp_wait<2>();
        else if (it == NITER - 2) cp_wait<1>();
        else                      cp_wait<0>();
        __syncthreads();

        if (it + 3 < NITER) { load_tile(it + 3); cp_commit(); }

        const int st = it & (NSTG - 1);
        const float* Ab = As + st * ASTAGE;
        const float* Bb = Bs + st * BSTAGE;

        #pragma unroll
        for (int ks = 0; ks < 2; ++ks) {
            const int kb = ks * 8;
            uint32_t af[2][4], bf[8][2];
            #pragma unroll
            for (int mt = 0; mt < 2; ++mt) {
                const int row = wm * 32 + mt * 16;
                af[mt][0] = __float_as_uint(Ab[(row + g)     * ASTR + kb + tg]);
                af[mt][1] = __float_as_uint(Ab[(row + g + 8) * ASTR + kb + tg]);
                af[mt][2] = __float_as_uint(Ab[(row + g)     * ASTR + kb + tg + 4]);
                af[mt][3] = __float_as_uint(Ab[(row + g + 8) * ASTR + kb + tg + 4]);
            }
            #pragma unroll
            for (int nt = 0; nt < 8; ++nt) {
                const int col = wn * 64 + nt * 8;
                const float2 v = *reinterpret_cast<const float2*>(
                    Bb + (col + g) * BSTR + kb + 2 * tg);
                bf[nt][0] = __float_as_uint(v.x);
                bf[nt][1] = __float_as_uint(v.y);
            }
            #pragma unroll
            for (int mt = 0; mt < 2; ++mt)
                #pragma unroll
                for (int nt = 0; nt < 8; ++nt)
                    mma_tf32(acc[mt][nt], af[mt], bf[nt]);
        }
    }

    // ---- epilogue: bias + scatter to [img, 1+patch, n] ----
    float bv[8][2];
    #pragma unroll
    for (int nt = 0; nt < 8; ++nt) {
        const int col = bn + wn * 64 + nt * 8 + tg * 2;
        bv[nt][0] = bias[col];
        bv[nt][1] = bias[col + 1];
    }

    #pragma unroll
    for (int mt = 0; mt < 2; ++mt) {
        #pragma unroll
        for (int rh = 0; rh < 2; ++rh) {
            const int m     = bm + wm * 32 + mt * 16 + rh * 8 + g;
            const int img   = m / NPATCH;
            const int patch = m - img * NPATCH;
            float* orow = out + ((size_t)img * 197 + patch + 1) * NDIM;
            #pragma unroll
            for (int nt = 0; nt < 8; ++nt) {
                const int col = bn + wn * 64 + nt * 8 + tg * 2;
                float2 v;
                v.x = acc[mt][nt][rh * 2 + 0] + bv[nt][0];
                v.y = acc[mt][nt][rh * 2 + 1] + bv[nt][1];
                *reinterpret_cast<float2*>(orow + col) = v;
            }
        }
    }

    // ---- fused CLS rows ----
    if (blockIdx.y == 0) {
        const int gid = blockIdx.x * 256 + tid;            // 0..1535
        const float4* c4 = (const float4*)cls;
        for (int i = gid; i < NIMG * (NDIM / 4); i += 1536) {
            const int img = i / (NDIM / 4);
            const int n4  = i - img * (NDIM / 4);
            reinterpret_cast<float4*>(out + (size_t)img * 197 * NDIM)[n4] = c4[n4];
        }
    }
}

extern "C" void kernel_launch(void* const* d_in, const int* in_sizes, int n_in,
                              void* d_out, int out_size) {
    const float* images = (const float*)d_in[0];
    const float* W      = (const float*)d_in[1];
    const float* b      = (const float*)d_in[2];
    const float* cls    = (const float*)d_in[3];
    float* out          = (float*)d_out;

    cudaFuncSetAttribute(vit_gemm, cudaFuncAttributeMaxDynamicSharedMemorySize, SMEM_BYTES);

    round_w<<<(NDIM * KDIM + 255) / 256, 256>>>(W);
    dim3 grid(NDIM / BN, MTOT / BM);   // (6, 196), n fastest for A L2 reuse
    vit_gemm<<<grid, 256, SMEM_BYTES>>>(images, b, cls, out);
}

// round 6
// speedup vs baseline: 1.9575x; 1.9133x over previous
#include <cuda_runtime.h>
#include <cstdint>

// ViT patch embedding, mma.sync tf32. GEMM M=25088, N=768, K=768 fused with
// patchify + bias + cls. BM=BN=128, BK=32 (128B rows), 3-stage cp.async ring,
// per-row 32B-rotation swizzle -> conflict-free STS(16B) and LDS.64 frag reads.
// k-pair slot permutation on BOTH operands (k=2tg,2tg+1) keeps math identical.

#define NPATCH  196
#define NIMG    128
#define KDIM    768
#define NDIM    768
#define MTOT    25088

#define BM 128
#define BN 128
#define BK 32
#define NITER (KDIM / BK)          // 24
#define STAGE_BYTES 32768          // A 16KB + B 16KB (128 rows x 128B each)
#define NSTG 3
#define SMEM_BYTES (NSTG * STAGE_BYTES)   // 98304

__device__ float W_pre[NDIM * KDIM];

__device__ __forceinline__ void mma_tf32(float* c, const uint32_t* a, const uint32_t* b) {
    asm volatile(
        "mma.sync.aligned.m16n8k8.row.col.f32.tf32.tf32.f32 "
        "{%0,%1,%2,%3}, {%4,%5,%6,%7}, {%8,%9}, {%0,%1,%2,%3};\n"
        : "+f"(c[0]), "+f"(c[1]), "+f"(c[2]), "+f"(c[3])
        : "r"(a[0]), "r"(a[1]), "r"(a[2]), "r"(a[3]), "r"(b[0]), "r"(b[1]));
}
__device__ __forceinline__ void cp16(uint32_t s, const void* g) {
    asm volatile("cp.async.cg.shared.global [%0], [%1], 16;\n" :: "r"(s), "l"(g));
}
__device__ __forceinline__ void cp_commit() { asm volatile("cp.async.commit_group;\n"); }
template <int N>
__device__ __forceinline__ void cp_wait() { asm volatile("cp.async.wait_group %0;\n" :: "n"(N)); }

// Pre-round W to tf32 (rna). No permutation (k-pairing handled in-kernel).
__global__ void round_w(const float* __restrict__ W) {
    int i = blockIdx.x * 256 + threadIdx.x;
    if (i < NDIM * KDIM) {
        uint32_t r;
        asm("cvt.rna.tf32.f32 %0, %1;" : "=r"(r) : "f"(W[i]));
        W_pre[i] = __uint_as_float(r);
    }
}

__global__ __launch_bounds__(256, 2) void vit_gemm(
    const float* __restrict__ images,
    const float* __restrict__ bias,
    const float* __restrict__ cls,
    float* __restrict__ out)
{
    extern __shared__ __align__(16) char smc[];

    const int tid  = threadIdx.x;
    const int lane = tid & 31;
    const int warp = tid >> 5;
    const int wm   = warp >> 1;     // 0..3 -> 32 rows
    const int wn   = warp & 1;      // 0..1 -> 64 cols
    const int g    = lane >> 2;     // 0..7
    const int tg   = lane & 3;      // 0..3

    const int bm = blockIdx.y * BM;
    const int bn = blockIdx.x * BN;

    // ---------------- loader mapping ----------------
    // warp w covers rows 16w..16w+15; slot i (0..3): row = 16w + 4i + q;
    // q = lane>>3 (0..3), chunk c = lane&7 (16B chunk within 128B row).
    const int lq = lane >> 3;
    const int lc = lane & 7;
    const uint32_t sw_off = (uint32_t)((16 * lc + 32 * lq) & 127);   // constant per thread

    // A gmem bases per slot (row -> image coords), chunk offset folded in.
    const float* asrc[4];
    const float* bsrc[4];
    uint32_t sts_row[4];
    #pragma unroll
    for (int i = 0; i < 4; ++i) {
        const int r   = 16 * warp + 4 * i + lq;   // 0..127
        const int m   = bm + r;
        const int img = m / NPATCH;
        const int pch = m - img * NPATCH;
        const int Pi  = pch / 14;
        const int Pj  = pch - Pi * 14;
        asrc[i] = images + (size_t)img * 150528 + (size_t)(Pi * 16 + (lc >> 2)) * 224
                         + Pj * 16 + (lc & 3) * 4;
        bsrc[i] = W_pre + (size_t)(bn + r) * KDIM + 4 * lc;
        sts_row[i] = (uint32_t)r * 128u + sw_off;
    }

    const uint32_t sbase = (uint32_t)__cvta_generic_to_shared(smc);

    auto load_tile = [&](int it) {
        const int st = it - (it / NSTG) * NSTG;          // it % 3
        const int k0 = it * BK;
        const int cch = k0 >> 8;                          // channel 0..2
        const int ph0 = (k0 >> 4) & 15;                   // patch row 0,2,..,14
        const size_t aoff = (size_t)cch * 50176 + (size_t)ph0 * 224;
        const uint32_t sa = sbase + (uint32_t)st * STAGE_BYTES;
        const uint32_t sb = sa + 16384;
        #pragma unroll
        for (int i = 0; i < 4; ++i) {
            cp16(sa + sts_row[i], asrc[i] + aoff);
            cp16(sb + sts_row[i], bsrc[i] + k0);
        }
    };

    float acc[2][8][4];
    #pragma unroll
    for (int mt = 0; mt < 2; ++mt)
        #pragma unroll
        for (int nt = 0; nt < 8; ++nt)
            #pragma unroll
            for (int r = 0; r < 4; ++r) acc[mt][nt][r] = 0.f;

    load_tile(0); cp_commit();
    load_tile(1); cp_commit();

    // frag read swizzle: row&3 == g&3 for all frag rows/cols (bases are mult of 4)
    const uint32_t fr_rot = (uint32_t)(32 * (g & 3)) ;    // + 8*tg + 32*ks, &127 per ks

    for (int it = 0; it < NITER; ++it) {
        if (it == NITER - 1) cp_wait<0>(); else cp_wait<1>();
        __syncthreads();

        const int st = it - (it / NSTG) * NSTG;
        const char* Ab = smc + st * STAGE_BYTES;
        const char* Bb = Ab + 16384;

        #pragma unroll
        for (int ks = 0; ks < 4; ++ks) {
            const uint32_t swz = (uint32_t)((32 * ks + 8 * tg + fr_rot) & 127);
            uint32_t af[2][4], bf[8][2];
            #pragma unroll
            for (int mt = 0; mt < 2; ++mt) {
                const int row = wm * 32 + mt * 16 + g;
                const float2 v0 = *reinterpret_cast<const float2*>(Ab + row * 128 + swz);
                const float2 v1 = *reinterpret_cast<const float2*>(Ab + (row + 8) * 128 + swz);
                af[mt][0] = __float_as_uint(v0.x);   // k = 2tg   (slot tg)
                af[mt][2] = __float_as_uint(v0.y);   // k = 2tg+1 (slot tg+4)
                af[mt][1] = __float_as_uint(v1.x);
                af[mt][3] = __float_as_uint(v1.y);
            }
            #pragma unroll
            for (int nt = 0; nt < 8; ++nt) {
                const int col = wn * 64 + nt * 8 + g;
                const float2 v = *reinterpret_cast<const float2*>(Bb + col * 128 + swz);
                bf[nt][0] = __float_as_uint(v.x);    // k = 2tg
                bf[nt][1] = __float_as_uint(v.y);    // k = 2tg+1
            }
            #pragma unroll
            for (int mt = 0; mt < 2; ++mt)
                #pragma unroll
                for (int nt = 0; nt < 8; ++nt)
                    mma_tf32(acc[mt][nt], af[mt], bf[nt]);

            if (ks == 0 && it + 2 < NITER) { load_tile(it + 2); cp_commit(); }
        }
    }

    // ---------------- epilogue: bias + scatter ----------------
    float bv[8][2];
    #pragma unroll
    for (int nt = 0; nt < 8; ++nt) {
        const int col = bn + wn * 64 + nt * 8 + tg * 2;
        bv[nt][0] = bias[col];
        bv[nt][1] = bias[col + 1];
    }

    #pragma unroll
    for (int mt = 0; mt < 2; ++mt) {
        #pragma unroll
        for (int rh = 0; rh < 2; ++rh) {
            const int m     = bm + wm * 32 + mt * 16 + rh * 8 + g;
            const int img   = m / NPATCH;
            const int patch = m - img * NPATCH;
            float* orow = out + ((size_t)img * 197 + patch + 1) * NDIM;
            #pragma unroll
            for (int nt = 0; nt < 8; ++nt) {
                const int col = bn + wn * 64 + nt * 8 + tg * 2;
                float2 v;
                v.x = acc[mt][nt][rh * 2 + 0] + bv[nt][0];
                v.y = acc[mt][nt][rh * 2 + 1] + bv[nt][1];
                *reinterpret_cast<float2*>(orow + col) = v;
            }
        }
    }

    // ---------------- fused CLS rows ----------------
    if (blockIdx.y == 0) {
        const int gid = blockIdx.x * 256 + tid;            // 0..1535
        const float4* c4 = (const float4*)cls;
        for (int i = gid; i < NIMG * (NDIM / 4); i += 1536) {
            const int img = i / (NDIM / 4);
            const int n4  = i - img * (NDIM / 4);
            reinterpret_cast<float4*>(out + (size_t)img * 197 * NDIM)[n4] = c4[n4];
        }
    }
}

extern "C" void kernel_launch(void* const* d_in, const int* in_sizes, int n_in,
                              void* d_out, int out_size) {
    const float* images = (const float*)d_in[0];
    const float* W      = (const float*)d_in[1];
    const float* b      = (const float*)d_in[2];
    const float* cls    = (const float*)d_in[3];
    float* out          = (float*)d_out;

    cudaFuncSetAttribute(vit_gemm, cudaFuncAttributeMaxDynamicSharedMemorySize, SMEM_BYTES);

    round_w<<<(NDIM * KDIM + 255) / 256, 256>>>(W);
    dim3 grid(NDIM / BN, MTOT / BM);   // (6, 196), n fastest for A L2 reuse
    vit_gemm<<<grid, 256, SMEM_BYTES>>>(images, b, cls, out);
}